// round 13
// baseline (speedup 1.0000x reference)
#include <cuda_runtime.h>
#include <cuda_bf16.h>
#include <cstdint>

static constexpr int cB  = 2;
static constexpr int cS  = 2048;
static constexpr int cE  = 1024;
static constexpr int cH  = 16;
static constexpr int cHD = 64;

// ---------------- scratch (device globals, allocation-free) ----------------
__device__ float g_wc[cE * cE];            // fp32 combined-weight scratch
__device__ float g_qh[cB * cS * cE];
__device__ float g_kh[cB * cS * cE];
__device__ float g_vh[cB * cS * cE];
__device__ float g_at[cB * cS * cE];
__device__ unsigned char g_mask[cB * cS * cS];
__device__ float g_biasc[3 * cE];
__device__ float g_zeros[cE];              // zero-initialized
// pre-split transposed weights: [n][k] bf16 hi/lo
__device__ __nv_bfloat16 g_wh_q[cE * cE],  g_wl_q[cE * cE];   // combined q
__device__ __nv_bfloat16 g_wh_k[cE * cE],  g_wl_k[cE * cE];   // combined k
__device__ __nv_bfloat16 g_wh_v[cE * cE],  g_wl_v[cE * cE];   // combined v
__device__ __nv_bfloat16 g_wh_o[cE * cE],  g_wl_o[cE * cE];
__device__ __nv_bfloat16 g_wh_hq[cE * cE], g_wl_hq[cE * cE];  // repacked Whq
__device__ __nv_bfloat16 g_wh_hk[cE * cE], g_wl_hk[cE * cE];
__device__ __nv_bfloat16 g_wh_hv[cE * cE], g_wl_hv[cE * cE];

// ---------------- helpers ----------------
__device__ __forceinline__ void splitbf(float x, unsigned short& h, unsigned short& l) {
    __nv_bfloat16 bh = __float2bfloat16(x);
    float r = x - __bfloat162float(bh);
    h = __bfloat16_as_ushort(bh);
    l = __bfloat16_as_ushort(__float2bfloat16(r));
}
__device__ __forceinline__ uint32_t pack2(unsigned short a, unsigned short b) {
    return (uint32_t)a | ((uint32_t)b << 16);
}
__device__ __forceinline__ void mma16(float c[4], const uint32_t a[4], const uint32_t b[2]) {
    asm volatile(
        "mma.sync.aligned.m16n8k16.row.col.f32.bf16.bf16.f32 "
        "{%0,%1,%2,%3}, {%4,%5,%6,%7}, {%8,%9}, {%0,%1,%2,%3};\n"
        : "+f"(c[0]), "+f"(c[1]), "+f"(c[2]), "+f"(c[3])
        : "r"(a[0]), "r"(a[1]), "r"(a[2]), "r"(a[3]), "r"(b[0]), "r"(b[1]));
}
__device__ __forceinline__ void ldsm4(uint32_t r[4], uint32_t addr) {
    asm volatile("ldmatrix.sync.aligned.m8n8.x4.shared.b16 {%0,%1,%2,%3}, [%4];"
        : "=r"(r[0]), "=r"(r[1]), "=r"(r[2]), "=r"(r[3]) : "r"(addr));
}
__device__ __forceinline__ void ldsm2(uint32_t r[2], uint32_t addr) {
    asm volatile("ldmatrix.sync.aligned.m8n8.x2.shared.b16 {%0,%1}, [%2];"
        : "=r"(r[0]), "=r"(r[1]) : "r"(addr));
}
__device__ __forceinline__ void ldsm2t(uint32_t r[2], uint32_t addr) {
    asm volatile("ldmatrix.sync.aligned.m8n8.x2.trans.shared.b16 {%0,%1}, [%2];"
        : "=r"(r[0]), "=r"(r[1]) : "r"(addr));
}

// ---------------- mask normalizer: any dtype -> uint8 0/1 ----------------
__global__ void mask_convert(const unsigned int* __restrict__ raw,
                             unsigned char* __restrict__ out)
{
    __shared__ int s_wide;
    if (threadIdx.x == 0) {
        int wide = 1;
        #pragma unroll 1
        for (int i = 0; i < 256; i++) {
            const unsigned int w = raw[i];
            if (w != 0u && w != 1u && w != 0x3F800000u) { wide = 0; break; }
        }
        s_wide = wide;
    }
    __syncthreads();
    const int i4 = blockIdx.x * blockDim.x + threadIdx.x;
    if (s_wide) {
        const uint4 w = ((const uint4*)raw)[i4];
        uchar4 r;
        r.x = (w.x != 0u); r.y = (w.y != 0u); r.z = (w.z != 0u); r.w = (w.w != 0u);
        ((uchar4*)out)[i4] = r;
    } else {
        ((unsigned int*)out)[i4] = raw[i4];
    }
}

// ---------------- weight prep: W[k][n] fp32 -> Th/Tl[n][k] bf16 -----------
__global__ void prep_w(const float* __restrict__ W,
                       __nv_bfloat16* __restrict__ Th, __nv_bfloat16* __restrict__ Tl)
{
    __shared__ float t[32][33];
    const int tx = threadIdx.x & 31, ty = threadIdx.x >> 5;
    const int k0 = blockIdx.y * 32, n0 = blockIdx.x * 32;
    #pragma unroll
    for (int i = 0; i < 4; i++)
        t[ty + 8 * i][tx] = W[(size_t)(k0 + ty + 8 * i) * cE + n0 + tx];
    __syncthreads();
    #pragma unroll
    for (int i = 0; i < 4; i++) {
        const float v = t[tx][ty + 8 * i];
        __nv_bfloat16 h = __float2bfloat16(v);
        const size_t o = (size_t)(n0 + ty + 8 * i) * cE + k0 + tx;
        Th[o] = h;
        Tl[o] = __float2bfloat16(v - __bfloat162float(h));
    }
}
// Wh[h][e][d] -> Th/Tl[n = h*64+d][k = e]
__global__ void prep_wh(const float* __restrict__ W,
                        __nv_bfloat16* __restrict__ Th, __nv_bfloat16* __restrict__ Tl)
{
    __shared__ float t[32][33];
    const int tx = threadIdx.x & 31, ty = threadIdx.x >> 5;
    const int d0 = blockIdx.x * 32, e0 = blockIdx.y * 32, h = blockIdx.z;
    #pragma unroll
    for (int i = 0; i < 4; i++)
        t[ty + 8 * i][tx] = W[(size_t)(h * cE + e0 + ty + 8 * i) * cHD + d0 + tx];
    __syncthreads();
    #pragma unroll
    for (int i = 0; i < 4; i++) {
        const float v = t[tx][ty + 8 * i];
        __nv_bfloat16 hh = __float2bfloat16(v);
        const size_t o = (size_t)(h * cHD + d0 + ty + 8 * i) * cE + e0 + tx;
        Th[o] = hh;
        Tl[o] = __float2bfloat16(v - __bfloat162float(hh));
    }
}

// ---------------- bias combine: out[n] = sum_k bq[k]*W2[k][n] + bh[n] ------
__global__ void bias_comb(const float* __restrict__ bq,
                          const __nv_bfloat16* __restrict__ Wh,
                          const __nv_bfloat16* __restrict__ Wl,
                          const float* __restrict__ bh, float* __restrict__ out)
{
    const int n = blockIdx.x * 8 + (threadIdx.x >> 5);
    const int lane = threadIdx.x & 31;
    float s = 0.f;
    for (int k = lane; k < cE; k += 32) {
        const float w = __bfloat162float(Wh[(size_t)n * cE + k]) +
                        __bfloat162float(Wl[(size_t)n * cE + k]);
        s += bq[k] * w;
    }
    #pragma unroll
    for (int off = 16; off; off >>= 1) s += __shfl_xor_sync(0xffffffffu, s, off);
    if (lane == 0) out[n] = s + bh[n];
}

// ---------------- GEMM: C[M,1024] = (A @ B + bias) * scale (bf16x3) --------
static constexpr int GBUF = 40960;            // 4 arrays * 128*40*2B
static constexpr int GSMEM = 2 * GBUF;        // 81920 B double-buffered

__global__ __launch_bounds__(256) void gemm_bf16x3(
    const float* __restrict__ A,
    const __nv_bfloat16* __restrict__ Bth, const __nv_bfloat16* __restrict__ Btl,
    const float* __restrict__ bias, float scale, float* __restrict__ C)
{
    extern __shared__ char smc[];
    const uint32_t sb = (uint32_t)__cvta_generic_to_shared(smc);
    const int tid  = threadIdx.x;
    const int lane = tid & 31, wid = tid >> 5;
    const int grp  = lane >> 2, qid = lane & 3;
    const int l7   = lane & 7, quad = lane >> 3;
    const int wm   = (wid & 1) * 64;
    const int wn   = (wid >> 1) * 32;
    const int bm   = blockIdx.y * 128;
    const int bn   = blockIdx.x * 128;
    const int fr   = tid >> 3, fc = (tid & 7) * 4;

    float acc[4][4][4];
    #pragma unroll
    for (int i = 0; i < 4; i++)
        #pragma unroll
        for (int j = 0; j < 4; j++)
            #pragma unroll
            for (int t = 0; t < 4; t++) acc[i][j][t] = 0.f;

    float4 ra[4]; uint2 rbh[4], rbl[4];

    auto load_regs = [&](int k0) {
        #pragma unroll
        for (int i = 0; i < 4; i++)
            ra[i] = *(const float4*)(A + (size_t)(bm + fr + 32 * i) * cE + k0 + fc);
        #pragma unroll
        for (int i = 0; i < 4; i++) {
            const size_t off = (size_t)(bn + fr + 32 * i) * cE + k0 + fc;
            rbh[i] = *(const uint2*)(Bth + off);
            rbl[i] = *(const uint2*)(Btl + off);
        }
    };
    auto store_buf = [&](int b) {
        char* base = smc + b * GBUF;
        #pragma unroll
        for (int i = 0; i < 4; i++) {
            unsigned short h0, l0, h1, l1, h2, l2, h3, l3;
            splitbf(ra[i].x, h0, l0); splitbf(ra[i].y, h1, l1);
            splitbf(ra[i].z, h2, l2); splitbf(ra[i].w, h3, l3);
            uint2 wh; wh.x = pack2(h0, h1); wh.y = pack2(h2, h3);
            uint2 wl; wl.x = pack2(l0, l1); wl.y = pack2(l2, l3);
            const int o = ((fr + 32 * i) * 40 + fc) * 2;
            *(uint2*)(base + o)         = wh;
            *(uint2*)(base + 10240 + o) = wl;
        }
        #pragma unroll
        for (int i = 0; i < 4; i++) {
            const int o = ((fr + 32 * i) * 40 + fc) * 2;
            *(uint2*)(base + 20480 + o) = rbh[i];
            *(uint2*)(base + 30720 + o) = rbl[i];
        }
    };
    auto compute = [&](int b) {
        const uint32_t base = sb + b * GBUF;
        const uint32_t Ah = base, Al = base + 10240, Bh = base + 20480, Bl = base + 30720;
        const int browA = (quad & 1) * 8 + l7;
        #pragma unroll
        for (int chunk = 0; chunk < 2; chunk++) {
            const int acol = chunk * 16 + (quad >> 1) * 8;
            const int bcol = chunk * 16 + ((lane >> 3) & 1) * 8;
            uint32_t bhf[4][2], blf[4][2];
            #pragma unroll
            for (int ni = 0; ni < 4; ni++) {
                const uint32_t boff = (uint32_t)(((wn + ni * 8 + l7) * 40 + bcol) * 2);
                ldsm2(bhf[ni], Bh + boff);
                ldsm2(blf[ni], Bl + boff);
            }
            #pragma unroll
            for (int mi = 0; mi < 4; mi++) {
                const uint32_t aoff = (uint32_t)(((wm + mi * 16 + browA) * 40 + acol) * 2);
                uint32_t ahf[4], alf[4];
                ldsm4(ahf, Ah + aoff);
                ldsm4(alf, Al + aoff);
                #pragma unroll
                for (int ni = 0; ni < 4; ni++) {
                    mma16(acc[mi][ni], ahf, bhf[ni]);
                    mma16(acc[mi][ni], alf, bhf[ni]);
                    mma16(acc[mi][ni], ahf, blf[ni]);
                }
            }
        }
    };

    load_regs(0);
    store_buf(0);
    __syncthreads();
    for (int kt = 0; kt < 32; kt++) {
        if (kt < 31) load_regs((kt + 1) * 32);
        compute(kt & 1);
        if (kt < 31) { store_buf((kt + 1) & 1); __syncthreads(); }
    }

    #pragma unroll
    for (int mi = 0; mi < 4; mi++) {
        const int r = bm + wm + mi * 16 + grp;
        #pragma unroll
        for (int ni = 0; ni < 4; ni++) {
            const int col = bn + wn + ni * 8 + 2 * qid;
            const float2 bv = *(const float2*)(bias + col);
            float2 t0 = make_float2((acc[mi][ni][0] + bv.x) * scale,
                                    (acc[mi][ni][1] + bv.y) * scale);
            *(float2*)(C + (size_t)r * cE + col) = t0;
            float2 t1 = make_float2((acc[mi][ni][2] + bv.x) * scale,
                                    (acc[mi][ni][3] + bv.y) * scale);
            *(float2*)(C + (size_t)(r + 8) * cE + col) = t1;
        }
    }
}

// ---------------- flash attention (Br=Bc=64, HD=64, 4 warps) ----------------
// smem bytes: Qh[64][72]bf16 @0, Ql @9216, Kh @18432 (P hi aliases),
//             Kl @27648 (P lo aliases), Vh @36864, Vl @46080, Ms u8 @55296
static constexpr int ASMEM = 59392;

__global__ __launch_bounds__(128) void flash_attn(
    const float* __restrict__ Qm, const float* __restrict__ Km,
    const float* __restrict__ Vm, const unsigned char* __restrict__ Mask,
    float* __restrict__ Om)
{
    extern __shared__ char smc[];
    const uint32_t sb = (uint32_t)__cvta_generic_to_shared(smc);
    char* Qh = smc;
    char* Ql = smc + 9216;
    char* Kh = smc + 18432;
    char* Kl = smc + 27648;
    char* Vh = smc + 36864;
    char* Vl = smc + 46080;
    unsigned char* Ms = (unsigned char*)(smc + 55296);
    const uint32_t Qh_b = sb, Ql_b = sb + 9216;
    const uint32_t Kh_b = sb + 18432, Kl_b = sb + 27648;
    const uint32_t Vh_b = sb + 36864, Vl_b = sb + 46080;

    const int tid = threadIdx.x, lane = tid & 31, w = tid >> 5;
    const int grp = lane >> 2, qid = lane & 3;
    const int l7  = lane & 7, quad = lane >> 3;
    const int browA = (quad & 1) * 8 + l7;
    const int b = blockIdx.y >> 4, h = blockIdx.y & 15;
    const int r0 = blockIdx.x * 64;

    const float* qb = Qm + (size_t)b * cS * cE + h * cHD;
    const float* kb = Km + (size_t)b * cS * cE + h * cHD;
    const float* vb = Vm + (size_t)b * cS * cE + h * cHD;
    const unsigned char* mb = Mask + (size_t)b * cS * cS;

    {   // Q tile, bf16 split (already pre-scaled by 0.125 in the projection)
        const int rw = tid >> 4, cc = (tid & 15) * 4;
        #pragma unroll
        for (int i = 0; i < 8; i++) {
            const int r = rw + 8 * i;
            float4 t = *(const float4*)(qb + (size_t)(r0 + r) * cE + cc);
            unsigned short h0, l0, h1, l1, h2, l2, h3, l3;
            splitbf(t.x, h0, l0); splitbf(t.y, h1, l1);
            splitbf(t.z, h2, l2); splitbf(t.w, h3, l3);
            uint2 wh; wh.x = pack2(h0, h1); wh.y = pack2(h2, h3);
            uint2 wl; wl.x = pack2(l0, l1); wl.y = pack2(l2, l3);
            const int o = (r * 72 + cc) * 2;
            *(uint2*)(Qh + o) = wh;
            *(uint2*)(Ql + o) = wl;
        }
    }

    const float NEG = -1e24f;
    float m0 = NEG, m1 = NEG, l0s = 0.f, l1s = 0.f;
    float o[8][4];
    #pragma unroll
    for (int i = 0; i < 8; i++)
        #pragma unroll
        for (int j = 0; j < 4; j++) o[i][j] = 0.f;

    const int rr0 = w * 16 + grp, rr1 = rr0 + 8;

    for (int jt = 0; jt < 32; jt++) {
        __syncthreads();  // prior P reads done before K/V overwrite
        {
            const int rw = tid >> 4, cc = (tid & 15) * 4;
            #pragma unroll
            for (int i = 0; i < 8; i++) {
                const int r = rw + 8 * i;
                float4 t = *(const float4*)(kb + (size_t)(jt * 64 + r) * cE + cc);
                unsigned short h0, l0b, h1, l1b, h2, l2b, h3, l3b;
                splitbf(t.x, h0, l0b); splitbf(t.y, h1, l1b);
                splitbf(t.z, h2, l2b); splitbf(t.w, h3, l3b);
                uint2 wh; wh.x = pack2(h0, h1); wh.y = pack2(h2, h3);
                uint2 wl; wl.x = pack2(l0b, l1b); wl.y = pack2(l2b, l3b);
                const int ob = (r * 72 + cc) * 2;
                *(uint2*)(Kh + ob) = wh;
                *(uint2*)(Kl + ob) = wl;
                float4 tv = *(const float4*)(vb + (size_t)(jt * 64 + r) * cE + cc);
                splitbf(tv.x, h0, l0b); splitbf(tv.y, h1, l1b);
                splitbf(tv.z, h2, l2b); splitbf(tv.w, h3, l3b);
                uint2 vhv; vhv.x = pack2(h0, h1); vhv.y = pack2(h2, h3);
                uint2 vlv; vlv.x = pack2(l0b, l1b); vlv.y = pack2(l2b, l3b);
                *(uint2*)(Vh + ob) = vhv;
                *(uint2*)(Vl + ob) = vlv;
            }
            const int mr = tid >> 2, mc = (tid & 3) * 16;
            *(int4*)(Ms + mr * 64 + mc) =
                *(const int4*)(mb + (size_t)(r0 + mr) * cS + jt * 64 + mc);
            *(int4*)(Ms + (mr + 32) * 64 + mc) =
                *(const int4*)(mb + (size_t)(r0 + mr + 32) * cS + jt * 64 + mc);
        }
        __syncthreads();

        // S = Q @ K^T (bf16x3, ldmatrix)
        float sf[8][4];
        #pragma unroll
        for (int i = 0; i < 8; i++)
            #pragma unroll
            for (int j = 0; j < 4; j++) sf[i][j] = 0.f;

        #pragma unroll
        for (int chunk = 0; chunk < 4; chunk++) {
            const int acol = chunk * 16 + (quad >> 1) * 8;
            const int bcol = chunk * 16 + ((lane >> 3) & 1) * 8;
            uint32_t qa[4], qlf[4];
            const uint32_t aoff = (uint32_t)(((w * 16 + browA) * 72 + acol) * 2);
            ldsm4(qa, Qh_b + aoff);
            ldsm4(qlf, Ql_b + aoff);
            #pragma unroll
            for (int nt = 0; nt < 8; nt++) {
                uint32_t kh2[2], kl2[2];
                const uint32_t boff = (uint32_t)(((nt * 8 + l7) * 72 + bcol) * 2);
                ldsm2(kh2, Kh_b + boff);
                ldsm2(kl2, Kl_b + boff);
                mma16(sf[nt], qa, kh2);
                mma16(sf[nt], qlf, kh2);
                mma16(sf[nt], qa, kl2);
            }
        }

        // mask, online softmax (scores already scaled via q)
        float tm0 = NEG, tm1 = NEG;
        #pragma unroll
        for (int nt = 0; nt < 8; nt++) {
            const int cb = nt * 8 + 2 * qid;
            float v0 = sf[nt][0]; if (Ms[rr0 * 64 + cb])     v0 = NEG;
            float v1 = sf[nt][1]; if (Ms[rr0 * 64 + cb + 1]) v1 = NEG;
            float v2 = sf[nt][2]; if (Ms[rr1 * 64 + cb])     v2 = NEG;
            float v3 = sf[nt][3]; if (Ms[rr1 * 64 + cb + 1]) v3 = NEG;
            sf[nt][0] = v0; sf[nt][1] = v1; sf[nt][2] = v2; sf[nt][3] = v3;
            tm0 = fmaxf(tm0, fmaxf(v0, v1));
            tm1 = fmaxf(tm1, fmaxf(v2, v3));
        }
        tm0 = fmaxf(tm0, __shfl_xor_sync(0xffffffffu, tm0, 1));
        tm0 = fmaxf(tm0, __shfl_xor_sync(0xffffffffu, tm0, 2));
        tm1 = fmaxf(tm1, __shfl_xor_sync(0xffffffffu, tm1, 1));
        tm1 = fmaxf(tm1, __shfl_xor_sync(0xffffffffu, tm1, 2));

        const float mn0 = fmaxf(m0, tm0), mn1 = fmaxf(m1, tm1);
        const float cor0 = __expf(m0 - mn0), cor1 = __expf(m1 - mn1);
        m0 = mn0; m1 = mn1;

        float rs0 = 0.f, rs1 = 0.f;
        #pragma unroll
        for (int nt = 0; nt < 8; nt++) {
            float p0 = __expf(sf[nt][0] - m0);
            float p1 = __expf(sf[nt][1] - m0);
            float p2 = __expf(sf[nt][2] - m1);
            float p3 = __expf(sf[nt][3] - m1);
            sf[nt][0] = p0; sf[nt][1] = p1; sf[nt][2] = p2; sf[nt][3] = p3;
            rs0 += p0 + p1; rs1 += p2 + p3;
        }
        rs0 += __shfl_xor_sync(0xffffffffu, rs0, 1);
        rs0 += __shfl_xor_sync(0xffffffffu, rs0, 2);
        rs1 += __shfl_xor_sync(0xffffffffu, rs1, 1);
        rs1 += __shfl_xor_sync(0xffffffffu, rs1, 2);
        l0s = l0s * cor0 + rs0;
        l1s = l1s * cor1 + rs1;

        #pragma unroll
        for (int nt = 0; nt < 8; nt++) {
            o[nt][0] *= cor0; o[nt][1] *= cor0;
            o[nt][2] *= cor1; o[nt][3] *= cor1;
        }

        __syncthreads();  // all K reads done before P overwrite (aliases Kh/Kl)
        #pragma unroll
        for (int nt = 0; nt < 8; nt++) {
            const int cb = nt * 8 + 2 * qid;
            unsigned short h0, l0v, h1, l1v;
            splitbf(sf[nt][0], h0, l0v); splitbf(sf[nt][1], h1, l1v);
            *(uint32_t*)(Kh + (rr0 * 72 + cb) * 2) = pack2(h0, h1);
            *(uint32_t*)(Kl + (rr0 * 72 + cb) * 2) = pack2(l0v, l1v);
            splitbf(sf[nt][2], h0, l0v); splitbf(sf[nt][3], h1, l1v);
            *(uint32_t*)(Kh + (rr1 * 72 + cb) * 2) = pack2(h0, h1);
            *(uint32_t*)(Kl + (rr1 * 72 + cb) * 2) = pack2(l0v, l1v);
        }
        __syncthreads();

        // O += P @ V (bf16x3, ldmatrix; V row-major [k][n] -> trans)
        #pragma unroll
        for (int chunk = 0; chunk < 4; chunk++) {
            uint32_t pa[4], plf[4];
            const uint32_t aoff =
                (uint32_t)(((w * 16 + browA) * 72 + chunk * 16 + (quad >> 1) * 8) * 2);
            ldsm4(pa, Kh_b + aoff);
            ldsm4(plf, Kl_b + aoff);
            const int krow = chunk * 16 + l7 + ((lane >> 3) & 1) * 8;
            #pragma unroll
            for (int nt = 0; nt < 8; nt++) {
                uint32_t vh2[2], vl2[2];
                const uint32_t boff = (uint32_t)((krow * 72 + nt * 8) * 2);
                ldsm2t(vh2, Vh_b + boff);
                ldsm2t(vl2, Vl_b + boff);
                mma16(o[nt], pa, vh2);
                mma16(o[nt], pa, vl2);
                mma16(o[nt], plf, vh2);
            }
        }
    }

    const float inv0 = 1.f / l0s, inv1 = 1.f / l1s;
    float* ob = Om + (size_t)b * cS * cE + h * cHD;
    #pragma unroll
    for (int nt = 0; nt < 8; nt++) {
        const int col = nt * 8 + 2 * qid;
        *(float2*)(ob + (size_t)(r0 + rr0) * cE + col) =
            make_float2(o[nt][0] * inv0, o[nt][1] * inv0);
        *(float2*)(ob + (size_t)(r0 + rr1) * cE + col) =
            make_float2(o[nt][2] * inv1, o[nt][3] * inv1);
    }
}

// ---------------- launcher ----------------
extern "C" void kernel_launch(void* const* d_in, const int* in_sizes, int n_in,
                              void* d_out, int out_size)
{
    (void)in_sizes; (void)n_in; (void)out_size;
    const float* q   = (const float*)d_in[0];
    const float* k   = (const float*)d_in[1];
    const float* v   = (const float*)d_in[2];
    const unsigned int* mask_raw = (const unsigned int*)d_in[3];
    const float* Wq  = (const float*)d_in[4];
    const float* bq  = (const float*)d_in[5];
    const float* Wk  = (const float*)d_in[6];
    const float* bk  = (const float*)d_in[7];
    const float* Wv  = (const float*)d_in[8];
    const float* bv  = (const float*)d_in[9];
    const float* Whq = (const float*)d_in[10];
    const float* bhq = (const float*)d_in[11];
    const float* Whk = (const float*)d_in[12];
    const float* bhk = (const float*)d_in[13];
    const float* Whv = (const float*)d_in[14];
    const float* bhv = (const float*)d_in[15];
    const float* Wo  = (const float*)d_in[16];
    const float* bo  = (const float*)d_in[17];
    float* out = (float*)d_out;

    float *p_wc, *p_qh, *p_kh, *p_vh, *p_at, *p_biasc, *p_zeros;
    unsigned char* p_mask;
    __nv_bfloat16 *wh_q, *wl_q, *wh_k, *wl_k, *wh_v, *wl_v, *wh_o, *wl_o;
    __nv_bfloat16 *wh_hq, *wl_hq, *wh_hk, *wl_hk, *wh_hv, *wl_hv;
    cudaGetSymbolAddress((void**)&p_wc, g_wc);
    cudaGetSymbolAddress((void**)&p_qh, g_qh);
    cudaGetSymbolAddress((void**)&p_kh, g_kh);
    cudaGetSymbolAddress((void**)&p_vh, g_vh);
    cudaGetSymbolAddress((void**)&p_at, g_at);
    cudaGetSymbolAddress((void**)&p_biasc, g_biasc);
    cudaGetSymbolAddress((void**)&p_zeros, g_zeros);
    cudaGetSymbolAddress((void**)&p_mask, g_mask);
    cudaGetSymbolAddress((void**)&wh_q, g_wh_q);   cudaGetSymbolAddress((void**)&wl_q, g_wl_q);
    cudaGetSymbolAddress((void**)&wh_k, g_wh_k);   cudaGetSymbolAddress((void**)&wl_k, g_wl_k);
    cudaGetSymbolAddress((void**)&wh_v, g_wh_v);   cudaGetSymbolAddress((void**)&wl_v, g_wl_v);
    cudaGetSymbolAddress((void**)&wh_o, g_wh_o);   cudaGetSymbolAddress((void**)&wl_o, g_wl_o);
    cudaGetSymbolAddress((void**)&wh_hq, g_wh_hq); cudaGetSymbolAddress((void**)&wl_hq, g_wl_hq);
    cudaGetSymbolAddress((void**)&wh_hk, g_wh_hk); cudaGetSymbolAddress((void**)&wl_hk, g_wl_hk);
    cudaGetSymbolAddress((void**)&wh_hv, g_wh_hv); cudaGetSymbolAddress((void**)&wl_hv, g_wl_hv);

    cudaFuncSetAttribute(gemm_bf16x3, cudaFuncAttributeMaxDynamicSharedMemorySize, GSMEM);
    cudaFuncSetAttribute(flash_attn,  cudaFuncAttributeMaxDynamicSharedMemorySize, ASMEM);

    const dim3 gbig(8, 32);    // N/128, M/128 for M=4096
    const dim3 gsm(8, 8);      // M=1024 weight-combine
    const dim3 gw(32, 32);
    const dim3 gwh(2, 32, 16);

    // ---- q chain (launch #6 is the big fused-q GEMM for ncu -s 5) ----
    prep_wh<<<gwh, 256>>>(Whq, wh_hq, wl_hq);                             // 1
    gemm_bf16x3<<<gsm, 256, GSMEM>>>(Wq, wh_hq, wl_hq, p_zeros, 1.f, p_wc); // 2
    prep_w<<<gw, 256>>>(p_wc, wh_q, wl_q);                                // 3
    bias_comb<<<128, 256>>>(bq, wh_hq, wl_hq, bhq, p_biasc);              // 4
    mask_convert<<<(cB * cS * cS) / 4 / 256, 256>>>(mask_raw, p_mask);    // 5
    gemm_bf16x3<<<gbig, 256, GSMEM>>>(q, wh_q, wl_q, p_biasc, 0.125f, p_qh); // 6 <- ncu
    // ---- k chain ----
    prep_wh<<<gwh, 256>>>(Whk, wh_hk, wl_hk);
    gemm_bf16x3<<<gsm, 256, GSMEM>>>(Wk, wh_hk, wl_hk, p_zeros, 1.f, p_wc);
    prep_w<<<gw, 256>>>(p_wc, wh_k, wl_k);
    bias_comb<<<128, 256>>>(bk, wh_hk, wl_hk, bhk, p_biasc + cE);
    gemm_bf16x3<<<gbig, 256, GSMEM>>>(k, wh_k, wl_k, p_biasc + cE, 1.f, p_kh);
    // ---- v chain ----
    prep_wh<<<gwh, 256>>>(Whv, wh_hv, wl_hv);
    gemm_bf16x3<<<gsm, 256, GSMEM>>>(Wv, wh_hv, wl_hv, p_zeros, 1.f, p_wc);
    prep_w<<<gw, 256>>>(p_wc, wh_v, wl_v);
    bias_comb<<<128, 256>>>(bv, wh_hv, wl_hv, bhv, p_biasc + 2 * cE);
    gemm_bf16x3<<<gbig, 256, GSMEM>>>(v, wh_v, wl_v, p_biasc + 2 * cE, 1.f, p_vh);
    // ---- attention + output projection ----
    flash_attn<<<dim3(32, 32), 128, ASMEM>>>(p_qh, p_kh, p_vh, p_mask, p_at);
    prep_w<<<gw, 256>>>(Wo, wh_o, wl_o);
    gemm_bf16x3<<<gbig, 256, GSMEM>>>(p_at, wh_o, wl_o, bo, 1.f, out);
}

// round 17
// speedup vs baseline: 1.0827x; 1.0827x over previous
#include <cuda_runtime.h>
#include <cuda_bf16.h>
#include <cstdint>

static constexpr int cB  = 2;
static constexpr int cS  = 2048;
static constexpr int cE  = 1024;
static constexpr int cH  = 16;
static constexpr int cHD = 64;

// ---------------- scratch (device globals, allocation-free) ----------------
__device__ float g_wc0[cE * cE];
__device__ float g_wc1[cE * cE];
__device__ float g_wc2[cE * cE];
__device__ float g_qh[cB * cS * cE];
__device__ float g_kh[cB * cS * cE];
__device__ float g_vh[cB * cS * cE];
__device__ float g_at[cB * cS * cE];
__device__ unsigned char g_mask[cB * cS * cS];
__device__ float g_biasc[3 * cE];
__device__ float g_zeros[cE];              // zero-initialized
// pre-split transposed weights: [n][k] bf16 hi/lo
__device__ __nv_bfloat16 g_wh_q[cE * cE],  g_wl_q[cE * cE];   // combined q
__device__ __nv_bfloat16 g_wh_k[cE * cE],  g_wl_k[cE * cE];   // combined k
__device__ __nv_bfloat16 g_wh_v[cE * cE],  g_wl_v[cE * cE];   // combined v
__device__ __nv_bfloat16 g_wh_o[cE * cE],  g_wl_o[cE * cE];
__device__ __nv_bfloat16 g_wh_hq[cE * cE], g_wl_hq[cE * cE];  // repacked Whq
__device__ __nv_bfloat16 g_wh_hk[cE * cE], g_wl_hk[cE * cE];
__device__ __nv_bfloat16 g_wh_hv[cE * cE], g_wl_hv[cE * cE];

// ---------------- helpers ----------------
__device__ __forceinline__ void splitbf(float x, unsigned short& h, unsigned short& l) {
    __nv_bfloat16 bh = __float2bfloat16(x);
    float r = x - __bfloat162float(bh);
    h = __bfloat16_as_ushort(bh);
    l = __bfloat16_as_ushort(__float2bfloat16(r));
}
__device__ __forceinline__ uint32_t pack2(unsigned short a, unsigned short b) {
    return (uint32_t)a | ((uint32_t)b << 16);
}
__device__ __forceinline__ void mma16(float c[4], const uint32_t a[4], const uint32_t b[2]) {
    asm volatile(
        "mma.sync.aligned.m16n8k16.row.col.f32.bf16.bf16.f32 "
        "{%0,%1,%2,%3}, {%4,%5,%6,%7}, {%8,%9}, {%0,%1,%2,%3};\n"
        : "+f"(c[0]), "+f"(c[1]), "+f"(c[2]), "+f"(c[3])
        : "r"(a[0]), "r"(a[1]), "r"(a[2]), "r"(a[3]), "r"(b[0]), "r"(b[1]));
}
__device__ __forceinline__ void ldsm4(uint32_t r[4], uint32_t addr) {
    asm volatile("ldmatrix.sync.aligned.m8n8.x4.shared.b16 {%0,%1,%2,%3}, [%4];"
        : "=r"(r[0]), "=r"(r[1]), "=r"(r[2]), "=r"(r[3]) : "r"(addr));
}
__device__ __forceinline__ void ldsm2(uint32_t r[2], uint32_t addr) {
    asm volatile("ldmatrix.sync.aligned.m8n8.x2.shared.b16 {%0,%1}, [%2];"
        : "=r"(r[0]), "=r"(r[1]) : "r"(addr));
}
__device__ __forceinline__ void ldsm2t(uint32_t r[2], uint32_t addr) {
    asm volatile("ldmatrix.sync.aligned.m8n8.x2.trans.shared.b16 {%0,%1}, [%2];"
        : "=r"(r[0]), "=r"(r[1]) : "r"(addr));
}

// ---------------- mask normalizer: any dtype -> uint8 0/1 ----------------
__global__ void mask_convert(const unsigned int* __restrict__ raw,
                             unsigned char* __restrict__ out)
{
    __shared__ int s_wide;
    if (threadIdx.x == 0) {
        int wide = 1;
        #pragma unroll 1
        for (int i = 0; i < 256; i++) {
            const unsigned int w = raw[i];
            if (w != 0u && w != 1u && w != 0x3F800000u) { wide = 0; break; }
        }
        s_wide = wide;
    }
    __syncthreads();
    const int i4 = blockIdx.x * blockDim.x + threadIdx.x;
    if (s_wide) {
        const uint4 w = ((const uint4*)raw)[i4];
        uchar4 r;
        r.x = (w.x != 0u); r.y = (w.y != 0u); r.z = (w.z != 0u); r.w = (w.w != 0u);
        ((uchar4*)out)[i4] = r;
    } else {
        ((unsigned int*)out)[i4] = raw[i4];
    }
}

// ------- batched prep_wh: Wh[h][e][d] -> Th/Tl[n = h*64+d][k = e], z=48 ----
__global__ void prep_wh3(const float* __restrict__ W0, const float* __restrict__ W1,
                         const float* __restrict__ W2,
                         __nv_bfloat16* __restrict__ Th0, __nv_bfloat16* __restrict__ Tl0,
                         __nv_bfloat16* __restrict__ Th1, __nv_bfloat16* __restrict__ Tl1,
                         __nv_bfloat16* __restrict__ Th2, __nv_bfloat16* __restrict__ Tl2)
{
    const int z = blockIdx.z, sel = z >> 4, h = z & 15;
    const float* W = sel == 0 ? W0 : (sel == 1 ? W1 : W2);
    __nv_bfloat16* Th = sel == 0 ? Th0 : (sel == 1 ? Th1 : Th2);
    __nv_bfloat16* Tl = sel == 0 ? Tl0 : (sel == 1 ? Tl1 : Tl2);
    __shared__ float t[32][33];
    const int tx = threadIdx.x & 31, ty = threadIdx.x >> 5;
    const int d0 = blockIdx.x * 32, e0 = blockIdx.y * 32;
    #pragma unroll
    for (int i = 0; i < 4; i++)
        t[ty + 8 * i][tx] = W[(size_t)(h * cE + e0 + ty + 8 * i) * cHD + d0 + tx];
    __syncthreads();
    #pragma unroll
    for (int i = 0; i < 4; i++) {
        const float v = t[tx][ty + 8 * i];
        __nv_bfloat16 hh = __float2bfloat16(v);
        const size_t o = (size_t)(h * cHD + d0 + ty + 8 * i) * cE + e0 + tx;
        Th[o] = hh;
        Tl[o] = __float2bfloat16(v - __bfloat162float(hh));
    }
}

// ------- batched prep_w: W[k][n] fp32 -> Th/Tl[n][k] bf16, z=4 -------------
__global__ void prep_w4(const float* __restrict__ W0, const float* __restrict__ W1,
                        const float* __restrict__ W2, const float* __restrict__ W3,
                        __nv_bfloat16* __restrict__ Th0, __nv_bfloat16* __restrict__ Tl0,
                        __nv_bfloat16* __restrict__ Th1, __nv_bfloat16* __restrict__ Tl1,
                        __nv_bfloat16* __restrict__ Th2, __nv_bfloat16* __restrict__ Tl2,
                        __nv_bfloat16* __restrict__ Th3, __nv_bfloat16* __restrict__ Tl3)
{
    const int z = blockIdx.z;
    const float* W = z == 0 ? W0 : (z == 1 ? W1 : (z == 2 ? W2 : W3));
    __nv_bfloat16* Th = z == 0 ? Th0 : (z == 1 ? Th1 : (z == 2 ? Th2 : Th3));
    __nv_bfloat16* Tl = z == 0 ? Tl0 : (z == 1 ? Tl1 : (z == 2 ? Tl2 : Tl3));
    __shared__ float t[32][33];
    const int tx = threadIdx.x & 31, ty = threadIdx.x >> 5;
    const int k0 = blockIdx.y * 32, n0 = blockIdx.x * 32;
    #pragma unroll
    for (int i = 0; i < 4; i++)
        t[ty + 8 * i][tx] = W[(size_t)(k0 + ty + 8 * i) * cE + n0 + tx];
    __syncthreads();
    #pragma unroll
    for (int i = 0; i < 4; i++) {
        const float v = t[tx][ty + 8 * i];
        __nv_bfloat16 h = __float2bfloat16(v);
        const size_t o = (size_t)(n0 + ty + 8 * i) * cE + k0 + tx;
        Th[o] = h;
        Tl[o] = __float2bfloat16(v - __bfloat162float(h));
    }
}

// ------- batched bias combine, z=3 ----------------------------------------
__global__ void bias_comb3(const float* __restrict__ b0, const float* __restrict__ b1,
                           const float* __restrict__ b2,
                           const __nv_bfloat16* __restrict__ Wh0, const __nv_bfloat16* __restrict__ Wl0,
                           const __nv_bfloat16* __restrict__ Wh1, const __nv_bfloat16* __restrict__ Wl1,
                           const __nv_bfloat16* __restrict__ Wh2, const __nv_bfloat16* __restrict__ Wl2,
                           const float* __restrict__ bh0, const float* __restrict__ bh1,
                           const float* __restrict__ bh2, float* __restrict__ out)
{
    const int z = blockIdx.y;
    const float* bq = z == 0 ? b0 : (z == 1 ? b1 : b2);
    const __nv_bfloat16* Wh = z == 0 ? Wh0 : (z == 1 ? Wh1 : Wh2);
    const __nv_bfloat16* Wl = z == 0 ? Wl0 : (z == 1 ? Wl1 : Wl2);
    const float* bh = z == 0 ? bh0 : (z == 1 ? bh1 : bh2);
    const int n = blockIdx.x * 8 + (threadIdx.x >> 5);
    const int lane = threadIdx.x & 31;
    float s = 0.f;
    for (int k = lane; k < cE; k += 32) {
        const float w = __bfloat162float(Wh[(size_t)n * cE + k]) +
                        __bfloat162float(Wl[(size_t)n * cE + k]);
        s += bq[k] * w;
    }
    #pragma unroll
    for (int off = 16; off; off >>= 1) s += __shfl_xor_sync(0xffffffffu, s, off);
    if (lane == 0) out[z * cE + n] = s + bh[n];
}

// ---------------- GEMM core (bf16x3, ldmatrix) -----------------------------
static constexpr int GBUF = 40960;            // 4 arrays * 128*40*2B
static constexpr int GSMEM = 2 * GBUF;        // 81920 B double-buffered

__device__ __forceinline__ void gemm_core(
    const float* __restrict__ A,
    const __nv_bfloat16* __restrict__ Bth, const __nv_bfloat16* __restrict__ Btl,
    const float* __restrict__ bias, float scale, float* __restrict__ C, char* smc)
{
    const uint32_t sb = (uint32_t)__cvta_generic_to_shared(smc);
    const int tid  = threadIdx.x;
    const int lane = tid & 31, wid = tid >> 5;
    const int grp  = lane >> 2, qid = lane & 3;
    const int l7   = lane & 7, quad = lane >> 3;
    const int wm   = (wid & 1) * 64;
    const int wn   = (wid >> 1) * 32;
    const int bm   = blockIdx.y * 128;
    const int bn   = blockIdx.x * 128;
    const int fr   = tid >> 3, fc = (tid & 7) * 4;

    float acc[4][4][4];
    #pragma unroll
    for (int i = 0; i < 4; i++)
        #pragma unroll
        for (int j = 0; j < 4; j++)
            #pragma unroll
            for (int t = 0; t < 4; t++) acc[i][j][t] = 0.f;

    float4 ra[4]; uint2 rbh[4], rbl[4];

    auto load_regs = [&](int k0) {
        #pragma unroll
        for (int i = 0; i < 4; i++)
            ra[i] = *(const float4*)(A + (size_t)(bm + fr + 32 * i) * cE + k0 + fc);
        #pragma unroll
        for (int i = 0; i < 4; i++) {
            const size_t off = (size_t)(bn + fr + 32 * i) * cE + k0 + fc;
            rbh[i] = *(const uint2*)(Bth + off);
            rbl[i] = *(const uint2*)(Btl + off);
        }
    };
    auto store_buf = [&](int b) {
        char* base = smc + b * GBUF;
        #pragma unroll
        for (int i = 0; i < 4; i++) {
            unsigned short h0, l0, h1, l1, h2, l2, h3, l3;
            splitbf(ra[i].x, h0, l0); splitbf(ra[i].y, h1, l1);
            splitbf(ra[i].z, h2, l2); splitbf(ra[i].w, h3, l3);
            uint2 wh; wh.x = pack2(h0, h1); wh.y = pack2(h2, h3);
            uint2 wl; wl.x = pack2(l0, l1); wl.y = pack2(l2, l3);
            const int o = ((fr + 32 * i) * 40 + fc) * 2;
            *(uint2*)(base + o)         = wh;
            *(uint2*)(base + 10240 + o) = wl;
        }
        #pragma unroll
        for (int i = 0; i < 4; i++) {
            const int o = ((fr + 32 * i) * 40 + fc) * 2;
            *(uint2*)(base + 20480 + o) = rbh[i];
            *(uint2*)(base + 30720 + o) = rbl[i];
        }
    };
    auto compute = [&](int b) {
        const uint32_t base = sb + b * GBUF;
        const uint32_t Ah = base, Al = base + 10240, Bh = base + 20480, Bl = base + 30720;
        const int browA = (quad & 1) * 8 + l7;
        #pragma unroll
        for (int chunk = 0; chunk < 2; chunk++) {
            const int acol = chunk * 16 + (quad >> 1) * 8;
            const int bcol = chunk * 16 + ((lane >> 3) & 1) * 8;
            uint32_t bhf[4][2], blf[4][2];
            #pragma unroll
            for (int ni = 0; ni < 4; ni++) {
                const uint32_t boff = (uint32_t)(((wn + ni * 8 + l7) * 40 + bcol) * 2);
                ldsm2(bhf[ni], Bh + boff);
                ldsm2(blf[ni], Bl + boff);
            }
            #pragma unroll
            for (int mi = 0; mi < 4; mi++) {
                const uint32_t aoff = (uint32_t)(((wm + mi * 16 + browA) * 40 + acol) * 2);
                uint32_t ahf[4], alf[4];
                ldsm4(ahf, Ah + aoff);
                ldsm4(alf, Al + aoff);
                #pragma unroll
                for (int ni = 0; ni < 4; ni++) {
                    mma16(acc[mi][ni], ahf, bhf[ni]);
                    mma16(acc[mi][ni], alf, bhf[ni]);
                    mma16(acc[mi][ni], ahf, blf[ni]);
                }
            }
        }
    };

    load_regs(0);
    store_buf(0);
    __syncthreads();
    for (int kt = 0; kt < 32; kt++) {
        if (kt < 31) load_regs((kt + 1) * 32);
        compute(kt & 1);
        if (kt < 31) { store_buf((kt + 1) & 1); __syncthreads(); }
    }

    #pragma unroll
    for (int mi = 0; mi < 4; mi++) {
        const int r = bm + wm + mi * 16 + grp;
        #pragma unroll
        for (int ni = 0; ni < 4; ni++) {
            const int col = bn + wn + ni * 8 + 2 * qid;
            const float2 bv = *(const float2*)(bias + col);
            float2 t0 = make_float2((acc[mi][ni][0] + bv.x) * scale,
                                    (acc[mi][ni][1] + bv.y) * scale);
            *(float2*)(C + (size_t)r * cE + col) = t0;
            float2 t1 = make_float2((acc[mi][ni][2] + bv.x) * scale,
                                    (acc[mi][ni][3] + bv.y) * scale);
            *(float2*)(C + (size_t)(r + 8) * cE + col) = t1;
        }
    }
}

__global__ __launch_bounds__(256) void gemm_bf16x3(
    const float* __restrict__ A,
    const __nv_bfloat16* __restrict__ Bth, const __nv_bfloat16* __restrict__ Btl,
    const float* __restrict__ bias, float scale, float* __restrict__ C)
{
    extern __shared__ char smc[];
    gemm_core(A, Bth, Btl, bias, scale, C, smc);
}

// batched over z=3: selects A/B/C/bias/scale per z
__global__ __launch_bounds__(256) void gemm3_bf16x3(
    const float* __restrict__ a0, const float* __restrict__ a1, const float* __restrict__ a2,
    const __nv_bfloat16* __restrict__ h0, const __nv_bfloat16* __restrict__ l0,
    const __nv_bfloat16* __restrict__ h1, const __nv_bfloat16* __restrict__ l1,
    const __nv_bfloat16* __restrict__ h2, const __nv_bfloat16* __restrict__ l2,
    const float* __restrict__ biasBase, int bstride,
    float s0, float s1, float s2,
    float* __restrict__ c0, float* __restrict__ c1, float* __restrict__ c2)
{
    extern __shared__ char smc[];
    const int z = blockIdx.z;
    const float* A = z == 0 ? a0 : (z == 1 ? a1 : a2);
    const __nv_bfloat16* Bh = z == 0 ? h0 : (z == 1 ? h1 : h2);
    const __nv_bfloat16* Bl = z == 0 ? l0 : (z == 1 ? l1 : l2);
    const float* bias = biasBase + z * bstride;
    const float scale = z == 0 ? s0 : (z == 1 ? s1 : s2);
    float* C = z == 0 ? c0 : (z == 1 ? c1 : c2);
    gemm_core(A, Bh, Bl, bias, scale, C, smc);
}

// ---------------- flash attention (Br=Bc=64, HD=64, 4 warps) ----------------
// smem bytes: Qh[64][72]bf16 @0, Ql @9216, Kh @18432 (P hi aliases),
//             Kl @27648 (P lo aliases), Vh @36864, Vl @46080, Ms u8 @55296
static constexpr int ASMEM = 59392;

__global__ __launch_bounds__(128) void flash_attn(
    const float* __restrict__ Qm, const float* __restrict__ Km,
    const float* __restrict__ Vm, const unsigned char* __restrict__ Mask,
    float* __restrict__ Om)
{
    extern __shared__ char smc[];
    const uint32_t sb = (uint32_t)__cvta_generic_to_shared(smc);
    char* Qh = smc;
    char* Ql = smc + 9216;
    char* Kh = smc + 18432;
    char* Kl = smc + 27648;
    char* Vh = smc + 36864;
    char* Vl = smc + 46080;
    unsigned char* Ms = (unsigned char*)(smc + 55296);
    const uint32_t Qh_b = sb, Ql_b = sb + 9216;
    const uint32_t Kh_b = sb + 18432, Kl_b = sb + 27648;
    const uint32_t Vh_b = sb + 36864, Vl_b = sb + 46080;

    const int tid = threadIdx.x, lane = tid & 31, w = tid >> 5;
    const int grp = lane >> 2, qid = lane & 3;
    const int l7  = lane & 7, quad = lane >> 3;
    const int browA = (quad & 1) * 8 + l7;
    const int b = blockIdx.y >> 4, h = blockIdx.y & 15;
    const int r0 = blockIdx.x * 64;

    const float* qb = Qm + (size_t)b * cS * cE + h * cHD;
    const float* kb = Km + (size_t)b * cS * cE + h * cHD;
    const float* vb = Vm + (size_t)b * cS * cE + h * cHD;
    const unsigned char* mb = Mask + (size_t)b * cS * cS;

    {   // Q tile, bf16 split (already pre-scaled by 0.125 in the projection)
        const int rw = tid >> 4, cc = (tid & 15) * 4;
        #pragma unroll
        for (int i = 0; i < 8; i++) {
            const int r = rw + 8 * i;
            float4 t = *(const float4*)(qb + (size_t)(r0 + r) * cE + cc);
            unsigned short h0, l0, h1, l1, h2, l2, h3, l3;
            splitbf(t.x, h0, l0); splitbf(t.y, h1, l1);
            splitbf(t.z, h2, l2); splitbf(t.w, h3, l3);
            uint2 wh; wh.x = pack2(h0, h1); wh.y = pack2(h2, h3);
            uint2 wl; wl.x = pack2(l0, l1); wl.y = pack2(l2, l3);
            const int o = (r * 72 + cc) * 2;
            *(uint2*)(Qh + o) = wh;
            *(uint2*)(Ql + o) = wl;
        }
    }

    const float NEG = -1e24f;
    float m0 = NEG, m1 = NEG, l0s = 0.f, l1s = 0.f;
    float o[8][4];
    #pragma unroll
    for (int i = 0; i < 8; i++)
        #pragma unroll
        for (int j = 0; j < 4; j++) o[i][j] = 0.f;

    const int rr0 = w * 16 + grp, rr1 = rr0 + 8;

    for (int jt = 0; jt < 32; jt++) {
        __syncthreads();  // prior P reads done before K/V overwrite
        {
            const int rw = tid >> 4, cc = (tid & 15) * 4;
            #pragma unroll
            for (int i = 0; i < 8; i++) {
                const int r = rw + 8 * i;
                float4 t = *(const float4*)(kb + (size_t)(jt * 64 + r) * cE + cc);
                unsigned short h0, l0b, h1, l1b, h2, l2b, h3, l3b;
                splitbf(t.x, h0, l0b); splitbf(t.y, h1, l1b);
                splitbf(t.z, h2, l2b); splitbf(t.w, h3, l3b);
                uint2 wh; wh.x = pack2(h0, h1); wh.y = pack2(h2, h3);
                uint2 wl; wl.x = pack2(l0b, l1b); wl.y = pack2(l2b, l3b);
                const int ob = (r * 72 + cc) * 2;
                *(uint2*)(Kh + ob) = wh;
                *(uint2*)(Kl + ob) = wl;
                float4 tv = *(const float4*)(vb + (size_t)(jt * 64 + r) * cE + cc);
                splitbf(tv.x, h0, l0b); splitbf(tv.y, h1, l1b);
                splitbf(tv.z, h2, l2b); splitbf(tv.w, h3, l3b);
                uint2 vhv; vhv.x = pack2(h0, h1); vhv.y = pack2(h2, h3);
                uint2 vlv; vlv.x = pack2(l0b, l1b); vlv.y = pack2(l2b, l3b);
                *(uint2*)(Vh + ob) = vhv;
                *(uint2*)(Vl + ob) = vlv;
            }
            const int mr = tid >> 2, mc = (tid & 3) * 16;
            *(int4*)(Ms + mr * 64 + mc) =
                *(const int4*)(mb + (size_t)(r0 + mr) * cS + jt * 64 + mc);
            *(int4*)(Ms + (mr + 32) * 64 + mc) =
                *(const int4*)(mb + (size_t)(r0 + mr + 32) * cS + jt * 64 + mc);
        }
        __syncthreads();

        // S = Q @ K^T (bf16x3, ldmatrix)
        float sf[8][4];
        #pragma unroll
        for (int i = 0; i < 8; i++)
            #pragma unroll
            for (int j = 0; j < 4; j++) sf[i][j] = 0.f;

        #pragma unroll
        for (int chunk = 0; chunk < 4; chunk++) {
            const int acol = chunk * 16 + (quad >> 1) * 8;
            const int bcol = chunk * 16 + ((lane >> 3) & 1) * 8;
            uint32_t qa[4], qlf[4];
            const uint32_t aoff = (uint32_t)(((w * 16 + browA) * 72 + acol) * 2);
            ldsm4(qa, Qh_b + aoff);
            ldsm4(qlf, Ql_b + aoff);
            #pragma unroll
            for (int nt = 0; nt < 8; nt++) {
                uint32_t kh2[2], kl2[2];
                const uint32_t boff = (uint32_t)(((nt * 8 + l7) * 72 + bcol) * 2);
                ldsm2(kh2, Kh_b + boff);
                ldsm2(kl2, Kl_b + boff);
                mma16(sf[nt], qa, kh2);
                mma16(sf[nt], qlf, kh2);
                mma16(sf[nt], qa, kl2);
            }
        }

        // mask, online softmax (scores already scaled via q)
        float tm0 = NEG, tm1 = NEG;
        #pragma unroll
        for (int nt = 0; nt < 8; nt++) {
            const int cb = nt * 8 + 2 * qid;
            float v0 = sf[nt][0]; if (Ms[rr0 * 64 + cb])     v0 = NEG;
            float v1 = sf[nt][1]; if (Ms[rr0 * 64 + cb + 1]) v1 = NEG;
            float v2 = sf[nt][2]; if (Ms[rr1 * 64 + cb])     v2 = NEG;
            float v3 = sf[nt][3]; if (Ms[rr1 * 64 + cb + 1]) v3 = NEG;
            sf[nt][0] = v0; sf[nt][1] = v1; sf[nt][2] = v2; sf[nt][3] = v3;
            tm0 = fmaxf(tm0, fmaxf(v0, v1));
            tm1 = fmaxf(tm1, fmaxf(v2, v3));
        }
        tm0 = fmaxf(tm0, __shfl_xor_sync(0xffffffffu, tm0, 1));
        tm0 = fmaxf(tm0, __shfl_xor_sync(0xffffffffu, tm0, 2));
        tm1 = fmaxf(tm1, __shfl_xor_sync(0xffffffffu, tm1, 1));
        tm1 = fmaxf(tm1, __shfl_xor_sync(0xffffffffu, tm1, 2));

        const float mn0 = fmaxf(m0, tm0), mn1 = fmaxf(m1, tm1);
        const float cor0 = __expf(m0 - mn0), cor1 = __expf(m1 - mn1);
        m0 = mn0; m1 = mn1;

        float rs0 = 0.f, rs1 = 0.f;
        #pragma unroll
        for (int nt = 0; nt < 8; nt++) {
            float p0 = __expf(sf[nt][0] - m0);
            float p1 = __expf(sf[nt][1] - m0);
            float p2 = __expf(sf[nt][2] - m1);
            float p3 = __expf(sf[nt][3] - m1);
            sf[nt][0] = p0; sf[nt][1] = p1; sf[nt][2] = p2; sf[nt][3] = p3;
            rs0 += p0 + p1; rs1 += p2 + p3;
        }
        rs0 += __shfl_xor_sync(0xffffffffu, rs0, 1);
        rs0 += __shfl_xor_sync(0xffffffffu, rs0, 2);
        rs1 += __shfl_xor_sync(0xffffffffu, rs1, 1);
        rs1 += __shfl_xor_sync(0xffffffffu, rs1, 2);
        l0s = l0s * cor0 + rs0;
        l1s = l1s * cor1 + rs1;

        #pragma unroll
        for (int nt = 0; nt < 8; nt++) {
            o[nt][0] *= cor0; o[nt][1] *= cor0;
            o[nt][2] *= cor1; o[nt][3] *= cor1;
        }

        __syncthreads();  // all K reads done before P overwrite (aliases Kh/Kl)
        #pragma unroll
        for (int nt = 0; nt < 8; nt++) {
            const int cb = nt * 8 + 2 * qid;
            unsigned short h0, l0v, h1, l1v;
            splitbf(sf[nt][0], h0, l0v); splitbf(sf[nt][1], h1, l1v);
            *(uint32_t*)(Kh + (rr0 * 72 + cb) * 2) = pack2(h0, h1);
            *(uint32_t*)(Kl + (rr0 * 72 + cb) * 2) = pack2(l0v, l1v);
            splitbf(sf[nt][2], h0, l0v); splitbf(sf[nt][3], h1, l1v);
            *(uint32_t*)(Kh + (rr1 * 72 + cb) * 2) = pack2(h0, h1);
            *(uint32_t*)(Kl + (rr1 * 72 + cb) * 2) = pack2(l0v, l1v);
        }
        __syncthreads();

        // O += P @ V (bf16x3, ldmatrix; V row-major [k][n] -> trans)
        #pragma unroll
        for (int chunk = 0; chunk < 4; chunk++) {
            uint32_t pa[4], plf[4];
            const uint32_t aoff =
                (uint32_t)(((w * 16 + browA) * 72 + chunk * 16 + (quad >> 1) * 8) * 2);
            ldsm4(pa, Kh_b + aoff);
            ldsm4(plf, Kl_b + aoff);
            const int krow = chunk * 16 + l7 + ((lane >> 3) & 1) * 8;
            #pragma unroll
            for (int nt = 0; nt < 8; nt++) {
                uint32_t vh2[2], vl2[2];
                const uint32_t boff = (uint32_t)((krow * 72 + nt * 8) * 2);
                ldsm2t(vh2, Vh_b + boff);
                ldsm2t(vl2, Vl_b + boff);
                mma16(o[nt], pa, vh2);
                mma16(o[nt], pa, vl2);
                mma16(o[nt], plf, vh2);
            }
        }
    }

    const float inv0 = 1.f / l0s, inv1 = 1.f / l1s;
    float* ob = Om + (size_t)b * cS * cE + h * cHD;
    #pragma unroll
    for (int nt = 0; nt < 8; nt++) {
        const int col = nt * 8 + 2 * qid;
        *(float2*)(ob + (size_t)(r0 + rr0) * cE + col) =
            make_float2(o[nt][0] * inv0, o[nt][1] * inv0);
        *(float2*)(ob + (size_t)(r0 + rr1) * cE + col) =
            make_float2(o[nt][2] * inv1, o[nt][3] * inv1);
    }
}

// ---------------- launcher ----------------
extern "C" void kernel_launch(void* const* d_in, const int* in_sizes, int n_in,
                              void* d_out, int out_size)
{
    (void)in_sizes; (void)n_in; (void)out_size;
    const float* q   = (const float*)d_in[0];
    const float* k   = (const float*)d_in[1];
    const float* v   = (const float*)d_in[2];
    const unsigned int* mask_raw = (const unsigned int*)d_in[3];
    const float* Wq  = (const float*)d_in[4];
    const float* bq  = (const float*)d_in[5];
    const float* Wk  = (const float*)d_in[6];
    const float* bk  = (const float*)d_in[7];
    const float* Wv  = (const float*)d_in[8];
    const float* bv  = (const float*)d_in[9];
    const float* Whq = (const float*)d_in[10];
    const float* bhq = (const float*)d_in[11];
    const float* Whk = (const float*)d_in[12];
    const float* bhk = (const float*)d_in[13];
    const float* Whv = (const float*)d_in[14];
    const float* bhv = (const float*)d_in[15];
    const float* Wo  = (const float*)d_in[16];
    const float* bo  = (const float*)d_in[17];
    float* out = (float*)d_out;

    float *p_wc0, *p_wc1, *p_wc2, *p_qh, *p_kh, *p_vh, *p_at, *p_biasc, *p_zeros;
    unsigned char* p_mask;
    __nv_bfloat16 *wh_q, *wl_q, *wh_k, *wl_k, *wh_v, *wl_v, *wh_o, *wl_o;
    __nv_bfloat16 *wh_hq, *wl_hq, *wh_hk, *wl_hk, *wh_hv, *wl_hv;
    cudaGetSymbolAddress((void**)&p_wc0, g_wc0);
    cudaGetSymbolAddress((void**)&p_wc1, g_wc1);
    cudaGetSymbolAddress((void**)&p_wc2, g_wc2);
    cudaGetSymbolAddress((void**)&p_qh, g_qh);
    cudaGetSymbolAddress((void**)&p_kh, g_kh);
    cudaGetSymbolAddress((void**)&p_vh, g_vh);
    cudaGetSymbolAddress((void**)&p_at, g_at);
    cudaGetSymbolAddress((void**)&p_biasc, g_biasc);
    cudaGetSymbolAddress((void**)&p_zeros, g_zeros);
    cudaGetSymbolAddress((void**)&p_mask, g_mask);
    cudaGetSymbolAddress((void**)&wh_q, g_wh_q);   cudaGetSymbolAddress((void**)&wl_q, g_wl_q);
    cudaGetSymbolAddress((void**)&wh_k, g_wh_k);   cudaGetSymbolAddress((void**)&wl_k, g_wl_k);
    cudaGetSymbolAddress((void**)&wh_v, g_wh_v);   cudaGetSymbolAddress((void**)&wl_v, g_wl_v);
    cudaGetSymbolAddress((void**)&wh_o, g_wh_o);   cudaGetSymbolAddress((void**)&wl_o, g_wl_o);
    cudaGetSymbolAddress((void**)&wh_hq, g_wh_hq); cudaGetSymbolAddress((void**)&wl_hq, g_wl_hq);
    cudaGetSymbolAddress((void**)&wh_hk, g_wh_hk); cudaGetSymbolAddress((void**)&wl_hk, g_wl_hk);
    cudaGetSymbolAddress((void**)&wh_hv, g_wh_hv); cudaGetSymbolAddress((void**)&wl_hv, g_wl_hv);

    cudaFuncSetAttribute(gemm_bf16x3,  cudaFuncAttributeMaxDynamicSharedMemorySize, GSMEM);
    cudaFuncSetAttribute(gemm3_bf16x3, cudaFuncAttributeMaxDynamicSharedMemorySize, GSMEM);
    cudaFuncSetAttribute(flash_attn,   cudaFuncAttributeMaxDynamicSharedMemorySize, ASMEM);

    // 1. mask
    mask_convert<<<(cB * cS * cS) / 4 / 256, 256>>>(mask_raw, p_mask);
    // 2. repack per-head weights (q,k,v batched, z=48)
    prep_wh3<<<dim3(2, 32, 48), 256>>>(Whq, Whk, Whv,
                                       wh_hq, wl_hq, wh_hk, wl_hk, wh_hv, wl_hv);
    // 3. weight-combine GEMMs Wc = Wg @ W2 (batched z=3, M=1024)
    gemm3_bf16x3<<<dim3(8, 8, 3), 256, GSMEM>>>(
        Wq, Wk, Wv,
        wh_hq, wl_hq, wh_hk, wl_hk, wh_hv, wl_hv,
        p_zeros, 0, 1.f, 1.f, 1.f,
        p_wc0, p_wc1, p_wc2);
    // 4. split/transpose combined weights + Wo (batched z=4)
    prep_w4<<<dim3(32, 32, 4), 256>>>(p_wc0, p_wc1, p_wc2, Wo,
                                      wh_q, wl_q, wh_k, wl_k, wh_v, wl_v, wh_o, wl_o);
    // 5. combined biases (batched)
    bias_comb3<<<dim3(128, 3), 256>>>(bq, bk, bv,
                                      wh_hq, wl_hq, wh_hk, wl_hk, wh_hv, wl_hv,
                                      bhq, bhk, bhv, p_biasc);
    // 6. big fused q/k/v projections (batched z=3, M=4096)  <- ncu -s 5 captures this
    gemm3_bf16x3<<<dim3(8, 32, 3), 256, GSMEM>>>(
        q, k, v,
        wh_q, wl_q, wh_k, wl_k, wh_v, wl_v,
        p_biasc, cE, 0.125f, 1.f, 1.f,
        p_qh, p_kh, p_vh);
    // 7. attention
    flash_attn<<<dim3(32, 32), 128, ASMEM>>>(p_qh, p_kh, p_vh, p_mask, p_at);
    // 8. output projection
    gemm_bf16x3<<<dim3(8, 32), 256, GSMEM>>>(p_at, wh_o, wl_o, bo, 1.f, out);
}